// round 4
// baseline (speedup 1.0000x reference)
#include <cuda_runtime.h>
#include <cuda_bf16.h>
#include <math.h>
#include <stdint.h>

// Problem constants
#define BB 8
#define TT 4096
#define DD 768
#define HH 12
#define HDIM 64
#define MM (BB*TT)          // 32768 rows

// Scratch (device globals: allocation-free rule)
__device__ float g_Q[(size_t)MM*DD];
__device__ float g_K[(size_t)MM*DD];
__device__ float g_V[(size_t)MM*DD];
__device__ float g_attn[(size_t)MM*DD];
__device__ float g_y[(size_t)MM*DD];

// ---------------------------------------------------------------------------
// TF32 GEMM: C[M,768] = A[M,768] @ W[768,768] + bias (+ res)
// Block tile 128x128, k-tile 32, 8 warps (2x4) of 64x32, double-buffered cp.async
// ---------------------------------------------------------------------------

__device__ __forceinline__ uint32_t f2tf(float f) {
    uint32_t u;
    asm("cvt.rna.tf32.f32 %0, %1;" : "=r"(u) : "f"(f));
    return u;
}

__device__ __forceinline__ void mma_tf32(float c[4], const uint32_t a[4], const uint32_t b[2]) {
    asm volatile(
        "mma.sync.aligned.m16n8k8.row.col.f32.tf32.tf32.f32 "
        "{%0,%1,%2,%3},{%4,%5,%6,%7},{%8,%9},{%0,%1,%2,%3};"
        : "+f"(c[0]), "+f"(c[1]), "+f"(c[2]), "+f"(c[3])
        : "r"(a[0]), "r"(a[1]), "r"(a[2]), "r"(a[3]), "r"(b[0]), "r"(b[1]));
}

#define A_STRIDE 36   // 32 + 4 pad (floats)
#define B_STRIDE 136  // 128 + 8 pad (floats)
#define A_TILE_F (128*A_STRIDE)   // 4608
#define B_TILE_F (32*B_STRIDE)    // 4352
#define GEMM_SMEM_BYTES ((2*A_TILE_F + 2*B_TILE_F)*4)  // 71680

__global__ void __launch_bounds__(256, 2)
gemm_tf32(const float* __restrict__ A, const float* __restrict__ W,
          const float* __restrict__ bias, const float* __restrict__ res,
          int outsel)
{
    extern __shared__ float sm[];
    float* As[2] = { sm, sm + A_TILE_F };
    float* Bs[2] = { sm + 2*A_TILE_F, sm + 2*A_TILE_F + B_TILE_F };

    const int tid  = threadIdx.x;
    const int lane = tid & 31;
    const int warp = tid >> 5;
    const int g    = lane >> 2;   // groupID
    const int tg   = lane & 3;    // thread-in-group
    const int wm0  = (warp >> 2) * 64;  // warp m offset
    const int wn0  = (warp & 3) * 32;   // warp n offset

    const int m0 = blockIdx.y * 128;
    const int n0 = blockIdx.x * 128;

    const float* Ap = A ? A : g_attn;
    float* C = (outsel == 0) ? g_Q : (outsel == 1) ? g_K : (outsel == 2) ? g_V : g_y;

    float acc[4][4][4];
#pragma unroll
    for (int i = 0; i < 4; i++)
#pragma unroll
        for (int j = 0; j < 4; j++)
#pragma unroll
            for (int r = 0; r < 4; r++) acc[i][j][r] = 0.f;

    auto loadA = [&](int buf, int k0) {
#pragma unroll
        for (int i = 0; i < 4; i++) {
            int idx = tid + i * 256;          // 0..1023 float4 slots
            int r  = idx >> 3;                // row 0..127
            int c4 = (idx & 7) * 4;           // float col 0,4,..28
            uint32_t d = (uint32_t)__cvta_generic_to_shared(As[buf] + r * A_STRIDE + c4);
            const float* gp = Ap + (size_t)(m0 + r) * DD + k0 + c4;
            asm volatile("cp.async.cg.shared.global [%0], [%1], 16;" :: "r"(d), "l"(gp));
        }
    };
    auto loadB = [&](int buf, int k0) {
#pragma unroll
        for (int i = 0; i < 4; i++) {
            int idx = tid + i * 256;
            int r  = idx >> 5;                // k-row 0..31
            int c4 = (idx & 31) * 4;          // n col 0,4,..124
            uint32_t d = (uint32_t)__cvta_generic_to_shared(Bs[buf] + r * B_STRIDE + c4);
            const float* gp = W + (size_t)(k0 + r) * DD + n0 + c4;
            asm volatile("cp.async.cg.shared.global [%0], [%1], 16;" :: "r"(d), "l"(gp));
        }
    };

    loadA(0, 0); loadB(0, 0);
    asm volatile("cp.async.commit_group;");

    const int NK = DD / 32;  // 24
    for (int kt = 0; kt < NK; kt++) {
        int buf = kt & 1;
        if (kt + 1 < NK) {
            loadA(buf ^ 1, (kt + 1) * 32);
            loadB(buf ^ 1, (kt + 1) * 32);
            asm volatile("cp.async.commit_group;");
            asm volatile("cp.async.wait_group 1;");
        } else {
            asm volatile("cp.async.wait_group 0;");
        }
        __syncthreads();

        const float* Asb = As[buf];
        const float* Bsb = Bs[buf];
#pragma unroll
        for (int ks = 0; ks < 4; ks++) {
            uint32_t af[4][4], bf[4][2];
#pragma unroll
            for (int i = 0; i < 4; i++) {
                const float* rp = Asb + (wm0 + i * 16 + g) * A_STRIDE + ks * 8;
                af[i][0] = f2tf(rp[tg]);
                af[i][1] = f2tf(rp[8 * A_STRIDE + tg]);
                af[i][2] = f2tf(rp[tg + 4]);
                af[i][3] = f2tf(rp[8 * A_STRIDE + tg + 4]);
            }
#pragma unroll
            for (int j = 0; j < 4; j++) {
                const float* bp = Bsb + (ks * 8 + tg) * B_STRIDE + wn0 + j * 8 + g;
                bf[j][0] = f2tf(bp[0]);
                bf[j][1] = f2tf(bp[4 * B_STRIDE]);
            }
#pragma unroll
            for (int i = 0; i < 4; i++)
#pragma unroll
                for (int j = 0; j < 4; j++)
                    mma_tf32(acc[i][j], af[i], bf[j]);
        }
        __syncthreads();
    }

    // Epilogue: + bias (+ residual), write
#pragma unroll
    for (int i = 0; i < 4; i++) {
#pragma unroll
        for (int j = 0; j < 4; j++) {
            int row = m0 + wm0 + i * 16 + g;
            int col = n0 + wn0 + j * 8 + tg * 2;
            size_t i0 = (size_t)row * DD + col;
            size_t i1 = i0 + (size_t)8 * DD;
            float b0v = bias[col], b1v = bias[col + 1];
            float2 v0 = make_float2(acc[i][j][0] + b0v, acc[i][j][1] + b1v);
            float2 v1 = make_float2(acc[i][j][2] + b0v, acc[i][j][3] + b1v);
            if (res) {
                float2 r0 = *(const float2*)(res + i0);
                float2 r1 = *(const float2*)(res + i1);
                v0.x += r0.x; v0.y += r0.y;
                v1.x += r1.x; v1.y += r1.y;
            }
            *(float2*)(C + i0) = v0;
            *(float2*)(C + i1) = v1;
        }
    }
}

// ---------------------------------------------------------------------------
// Local attention: each query attends to {t-3, t, t+3}. One warp per (b,t,h).
// ---------------------------------------------------------------------------
__global__ void __launch_bounds__(256)
attn_kernel()
{
    const int warp = threadIdx.x >> 5;
    const int lane = threadIdx.x & 31;
    const int gw = blockIdx.x * 8 + warp;   // 0 .. B*T*H-1
    const int h  = gw % HH;
    const int bt = gw / HH;                 // b*T + t
    const int t  = bt & (TT - 1);
    const int b  = bt >> 12;

    const size_t qb = (size_t)bt * DD + h * HDIM + lane;
    const float q0 = g_Q[qb];
    const float q1 = g_Q[qb + 32];

    float w[3];
    size_t kb[3];
#pragma unroll
    for (int o = 0; o < 3; o++) {
        int tt = t + (o - 1) * 3;
        bool valid = (tt >= 0) && (tt < TT);
        int ttc = valid ? tt : t;
        kb[o] = ((size_t)(b * TT + ttc)) * DD + h * HDIM + lane;
        float p = q0 * g_K[kb[o]] + q1 * g_K[kb[o] + 32];
#pragma unroll
        for (int d2 = 16; d2 > 0; d2 >>= 1)
            p += __shfl_xor_sync(0xffffffffu, p, d2);
        w[o] = valid ? p * 0.125f : -INFINITY;   // 1/sqrt(64)
    }
    float m = fmaxf(w[0], fmaxf(w[1], w[2]));
    float s = 0.f;
#pragma unroll
    for (int o = 0; o < 3; o++) { w[o] = __expf(w[o] - m); s += w[o]; }
    float inv = 1.f / s;

    float a0 = 0.f, a1 = 0.f;
#pragma unroll
    for (int o = 0; o < 3; o++) {
        a0 += w[o] * g_V[kb[o]];
        a1 += w[o] * g_V[kb[o] + 32];
    }
    g_attn[qb]      = a0 * inv;
    g_attn[qb + 32] = a1 * inv;
}

// ---------------------------------------------------------------------------
// LayerNorm over last dim (768), one block per row. Input g_y (already has
// residual added by the O-GEMM epilogue).
// ---------------------------------------------------------------------------
__global__ void __launch_bounds__(256)
ln_kernel(const float* __restrict__ gamma, const float* __restrict__ beta,
          float* __restrict__ out)
{
    const int row = blockIdx.x;
    const int tid = threadIdx.x;
    const int lane = tid & 31;
    const int warp = tid >> 5;
    const float* y = g_y + (size_t)row * DD;

    float v[3];
    float s = 0.f, sq = 0.f;
#pragma unroll
    for (int j = 0; j < 3; j++) {
        v[j] = y[tid + j * 256];
        s += v[j];
        sq += v[j] * v[j];
    }
#pragma unroll
    for (int d2 = 16; d2 > 0; d2 >>= 1) {
        s  += __shfl_xor_sync(0xffffffffu, s, d2);
        sq += __shfl_xor_sync(0xffffffffu, sq, d2);
    }
    __shared__ float rs[8], rq[8];
    if (lane == 0) { rs[warp] = s; rq[warp] = sq; }
    __syncthreads();
    if (warp == 0) {
        float a  = (lane < 8) ? rs[lane] : 0.f;
        float b2 = (lane < 8) ? rq[lane] : 0.f;
#pragma unroll
        for (int d2 = 4; d2 > 0; d2 >>= 1) {
            a  += __shfl_xor_sync(0xffffffffu, a, d2);
            b2 += __shfl_xor_sync(0xffffffffu, b2, d2);
        }
        if (lane == 0) { rs[0] = a; rq[0] = b2; }
    }
    __syncthreads();
    const float mu   = rs[0] * (1.f / 768.f);
    const float var  = rq[0] * (1.f / 768.f) - mu * mu;
    const float rstd = rsqrtf(var + 1e-5f);
#pragma unroll
    for (int j = 0; j < 3; j++) {
        int i = tid + j * 256;
        out[(size_t)row * DD + i] = (v[j] - mu) * rstd * gamma[i] + beta[i];
    }
}

// ---------------------------------------------------------------------------
extern "C" void kernel_launch(void* const* d_in, const int* in_sizes, int n_in,
                              void* d_out, int out_size)
{
    const float* x     = (const float*)d_in[0];
    const float* Wq    = (const float*)d_in[1];
    const float* bq    = (const float*)d_in[2];
    const float* Wk    = (const float*)d_in[3];
    const float* bk    = (const float*)d_in[4];
    const float* Wv    = (const float*)d_in[5];
    const float* bv    = (const float*)d_in[6];
    const float* Wo    = (const float*)d_in[7];
    const float* bo    = (const float*)d_in[8];
    const float* gamma = (const float*)d_in[9];
    const float* beta  = (const float*)d_in[10];
    float* out = (float*)d_out;

    cudaFuncSetAttribute(gemm_tf32, cudaFuncAttributeMaxDynamicSharedMemorySize,
                         GEMM_SMEM_BYTES);

    dim3 ggrid(DD / 128, MM / 128);  // (6, 256)
    gemm_tf32<<<ggrid, 256, GEMM_SMEM_BYTES>>>(x, Wq, bq, nullptr, 0);
    gemm_tf32<<<ggrid, 256, GEMM_SMEM_BYTES>>>(x, Wk, bk, nullptr, 1);
    gemm_tf32<<<ggrid, 256, GEMM_SMEM_BYTES>>>(x, Wv, bv, nullptr, 2);

    attn_kernel<<<(BB * TT * HH) / 8, 256>>>();

    gemm_tf32<<<ggrid, 256, GEMM_SMEM_BYTES>>>(nullptr, Wo, bo, x, 3);

    ln_kernel<<<MM, 256>>>(gamma, beta, out);
}

// round 8
// speedup vs baseline: 2.2959x; 2.2959x over previous
#include <cuda_runtime.h>
#include <cuda_fp16.h>
#include <math.h>
#include <stdint.h>

#define BB 8
#define TT 4096
#define DD 768
#define HH 12
#define MM (BB*TT)          // 32768

// Scratch (device globals: allocation-free rule)
__device__ float  g_Q[(size_t)MM*DD];
__device__ float  g_K[(size_t)MM*DD];
__device__ float  g_V[(size_t)MM*DD];
__device__ float  g_y[(size_t)MM*DD];
__device__ __half g_xh[(size_t)MM*DD];        // x in fp16
__device__ __half g_attnh[(size_t)MM*DD];     // attention output in fp16
__device__ __half g_Wth[4][(size_t)DD*DD];    // transposed weights, fp16 ([n][k])

// ===========================================================================
// fp32 -> fp16 conversion: 8 elements per thread (2x float4 in, 16B out)
// ===========================================================================
__global__ void __launch_bounds__(256)
f2h_kernel(const float* __restrict__ src)
{
    size_t i = ((size_t)blockIdx.x * 256 + threadIdx.x) * 8;
    float4 a = *(const float4*)(src + i);
    float4 b = *(const float4*)(src + i + 4);
    __half2 h[4];
    h[0] = __floats2half2_rn(a.x, a.y);
    h[1] = __floats2half2_rn(a.z, a.w);
    h[2] = __floats2half2_rn(b.x, b.y);
    h[3] = __floats2half2_rn(b.z, b.w);
    *(uint2*)(g_xh + i)     = *(uint2*)&h[0];
    *(uint2*)(g_xh + i + 4) = *(uint2*)&h[2];
}

// ===========================================================================
// Weight transpose + fp16 convert: g_Wth[which][n][k] = (half)W[k][n]
// ===========================================================================
__global__ void __launch_bounds__(256)
transpose_w(const float* __restrict__ W, int which)
{
    __shared__ float t[32][33];
    __half* Wt = g_Wth[which];
    int x  = blockIdx.x * 32 + threadIdx.x;
    int y0 = blockIdx.y * 32 + threadIdx.y;
#pragma unroll
    for (int i = 0; i < 4; i++)
        t[threadIdx.y + 8 * i][threadIdx.x] = W[(size_t)(y0 + 8 * i) * DD + x];
    __syncthreads();
    int x2 = blockIdx.y * 32 + threadIdx.x;
    int y2 = blockIdx.x * 32 + threadIdx.y;
#pragma unroll
    for (int i = 0; i < 4; i++)
        Wt[(size_t)(y2 + 8 * i) * DD + x2] = __float2half(t[threadIdx.x][threadIdx.y + 8 * i]);
}

// ===========================================================================
// FP16 tensor-core GEMM: C[128x128 tile] = A[M,768](h) @ Wt^T(h) + bias (+res)
// A row-major [m][k], B = Wt [n][k] (both k-contiguous). mma.m16n8k16.
// k-tile = 64 halves (128B rows), chunk-XOR swizzle, 3-stage cp.async ring.
// A operand selected DEVICE-SIDE via asel (0 = g_xh, 1 = g_attnh) — passing
// __device__ symbols from host code is invalid (reads the host shadow).
// ===========================================================================
#define KH 64                 // halves per k-tile
#define NKT (DD/KH)           // 12
#define STG_BYTES 16384       // 128 rows x 128B (per operand)
#define NSTG 3
#define GSMEM (NSTG * 2 * STG_BYTES)   // 98304

__device__ __forceinline__ void ldsm_x4(uint32_t* r, uint32_t addr) {
    asm volatile("ldmatrix.sync.aligned.m8n8.x4.shared.b16 {%0,%1,%2,%3}, [%4];"
                 : "=r"(r[0]), "=r"(r[1]), "=r"(r[2]), "=r"(r[3]) : "r"(addr));
}
__device__ __forceinline__ void mma_f16(float c[4], const uint32_t a[4], const uint32_t b[2]) {
    asm volatile(
        "mma.sync.aligned.m16n8k16.row.col.f32.f16.f16.f32 "
        "{%0,%1,%2,%3},{%4,%5,%6,%7},{%8,%9},{%0,%1,%2,%3};"
        : "+f"(c[0]), "+f"(c[1]), "+f"(c[2]), "+f"(c[3])
        : "r"(a[0]), "r"(a[1]), "r"(a[2]), "r"(a[3]), "r"(b[0]), "r"(b[1]));
}

__global__ void __launch_bounds__(256, 2)
gemm_h(int asel, const float* __restrict__ bias,
       const float* __restrict__ res, int wsel, int csel)
{
    extern __shared__ char smem[];
    const uint32_t sbase = (uint32_t)__cvta_generic_to_shared(smem);

    const int tid  = threadIdx.x;
    const int warp = tid >> 5;
    const int lane = tid & 31;
    const int g    = lane >> 2;
    const int tg   = lane & 3;
    const int wm0  = (warp >> 2) * 64;   // warp m offset (2 rows of warps)
    const int wn0  = (warp & 3) * 32;    // warp n offset (4 cols of warps)

    const int m0 = blockIdx.y * 128;
    const int n0 = blockIdx.x * 128;

    const __half* Ap = (asel == 0) ? g_xh : g_attnh;   // device-side symbol ref
    const __half* Bt = g_Wth[wsel];
    float* C = (csel == 0) ? g_Q : (csel == 1) ? g_K : (csel == 2) ? g_V : g_y;

    float acc[4][4][4];
#pragma unroll
    for (int i = 0; i < 4; i++)
#pragma unroll
        for (int j = 0; j < 4; j++)
#pragma unroll
            for (int r = 0; r < 4; r++) acc[i][j][r] = 0.f;

    // ---- stage loader: 16B chunks, 128B rows, chunk-XOR swizzle ----
    auto load_stage = [&](int kt) {
        const int slot = kt % NSTG;
        const int k0 = kt * KH;
        const uint32_t abase = sbase + slot * 2 * STG_BYTES;
        const uint32_t bbase = abase + STG_BYTES;
#pragma unroll
        for (int i = 0; i < 4; i++) {               // A: 128 rows x 8 chunks
            int idx = tid + i * 256;
            int r = idx >> 3, c = idx & 7;
            uint32_t sw = (uint32_t)(c ^ (r & 7)) * 16;
            const __half* gp = Ap + (size_t)(m0 + r) * DD + k0 + c * 8;
            asm volatile("cp.async.cg.shared.global [%0], [%1], 16;"
                         :: "r"(abase + (uint32_t)r * 128 + sw), "l"(gp));
        }
#pragma unroll
        for (int i = 0; i < 4; i++) {               // B: 128 n-rows x 8 chunks
            int idx = tid + i * 256;
            int r = idx >> 3, c = idx & 7;
            uint32_t sw = (uint32_t)(c ^ (r & 7)) * 16;
            const __half* gp = Bt + (size_t)(n0 + r) * DD + k0 + c * 8;
            asm volatile("cp.async.cg.shared.global [%0], [%1], 16;"
                         :: "r"(bbase + (uint32_t)r * 128 + sw), "l"(gp));
        }
        asm volatile("cp.async.commit_group;");
    };

    load_stage(0);
    load_stage(1);

    for (int kt = 0; kt < NKT; kt++) {
        const int slot = kt % NSTG;
        if (kt + 2 < NKT) load_stage(kt + 2);
        if (kt + 2 < NKT)      asm volatile("cp.async.wait_group 2;");
        else if (kt + 1 < NKT) asm volatile("cp.async.wait_group 1;");
        else                   asm volatile("cp.async.wait_group 0;");
        __syncthreads();

        const uint32_t abase = sbase + slot * 2 * STG_BYTES;
        const uint32_t bbase = abase + STG_BYTES;

#pragma unroll
        for (int ks = 0; ks < 4; ks++) {            // 4 x k16 per k-tile
            uint32_t af[4][4], bf[2][4];
            // A fragments: one x4 per m16 tile
#pragma unroll
            for (int i = 0; i < 4; i++) {
                int row = wm0 + i * 16 + (lane & 15);
                int chunk = ks * 2 + (lane >> 4);
                uint32_t addr = abase + (uint32_t)row * 128
                              + (uint32_t)((chunk ^ (row & 7)) * 16);
                ldsm_x4(af[i], addr);
            }
            // B fragments: one x4 covers two n8 tiles (jp -> j=2jp, 2jp+1)
#pragma unroll
            for (int jp = 0; jp < 2; jp++) {
                int nrow = wn0 + jp * 16 + (lane & 7) + ((lane >> 4) << 3);
                int chunk = ks * 2 + ((lane >> 3) & 1);
                uint32_t addr = bbase + (uint32_t)nrow * 128
                              + (uint32_t)((chunk ^ (nrow & 7)) * 16);
                ldsm_x4(bf[jp], addr);
            }
#pragma unroll
            for (int i = 0; i < 4; i++)
#pragma unroll
                for (int j = 0; j < 4; j++)
                    mma_f16(acc[i][j], af[i], bf[j >> 1] + (j & 1) * 2);
        }
        __syncthreads();
    }

    // ---- epilogue: +bias (+res), float2 stores ----
#pragma unroll
    for (int i = 0; i < 4; i++) {
#pragma unroll
        for (int j = 0; j < 4; j++) {
            int row = m0 + wm0 + i * 16 + g;
            int col = n0 + wn0 + j * 8 + tg * 2;
            size_t i0 = (size_t)row * DD + col;
            size_t i1 = i0 + (size_t)8 * DD;
            float b0v = bias[col], b1v = bias[col + 1];
            float2 v0 = make_float2(acc[i][j][0] + b0v, acc[i][j][1] + b1v);
            float2 v1 = make_float2(acc[i][j][2] + b0v, acc[i][j][3] + b1v);
            if (res) {
                float2 r0 = *(const float2*)(res + i0);
                float2 r1 = *(const float2*)(res + i1);
                v0.x += r0.x; v0.y += r0.y;
                v1.x += r1.x; v1.y += r1.y;
            }
            *(float2*)(C + i0) = v0;
            *(float2*)(C + i1) = v1;
        }
    }
}

// ===========================================================================
// Local attention: query attends {t-3, t, t+3}. One warp per (b,t,h).
// Q/K/V fp32 in, fp16 out (feeds O-GEMM).
// ===========================================================================
__global__ void __launch_bounds__(256)
attn_kernel()
{
    const int warp = threadIdx.x >> 5;
    const int lane = threadIdx.x & 31;
    const int gw = blockIdx.x * 8 + warp;   // 0 .. B*T*H-1
    const int h  = gw % HH;
    const int bt = gw / HH;
    const int t  = bt & (TT - 1);
    const int b  = bt >> 12;

    const size_t qb = (size_t)bt * (DD / 2) + h * 32 + lane;   // float2 index
    const float2 q = ((const float2*)g_Q)[qb];

    float w[3];
    size_t kb[3];
#pragma unroll
    for (int o = 0; o < 3; o++) {
        int tt = t + (o - 1) * 3;
        bool valid = (tt >= 0) && (tt < TT);
        int ttc = valid ? tt : t;
        kb[o] = ((size_t)(b * TT + ttc)) * (DD / 2) + h * 32 + lane;
        float2 k2 = ((const float2*)g_K)[kb[o]];
        float p = q.x * k2.x + q.y * k2.y;
#pragma unroll
        for (int d2 = 16; d2 > 0; d2 >>= 1)
            p += __shfl_xor_sync(0xffffffffu, p, d2);
        w[o] = valid ? p * 0.125f : -INFINITY;   // 1/sqrt(64)
    }
    float m = fmaxf(w[0], fmaxf(w[1], w[2]));
    float s = 0.f;
#pragma unroll
    for (int o = 0; o < 3; o++) { w[o] = __expf(w[o] - m); s += w[o]; }
    float inv = 1.f / s;

    float a0 = 0.f, a1 = 0.f;
#pragma unroll
    for (int o = 0; o < 3; o++) {
        float2 v2 = ((const float2*)g_V)[kb[o]];
        a0 += w[o] * v2.x;
        a1 += w[o] * v2.y;
    }
    ((__half2*)g_attnh)[qb] = __floats2half2_rn(a0 * inv, a1 * inv);
}

// ===========================================================================
// LayerNorm over last dim (768), one block per row.
// ===========================================================================
__global__ void __launch_bounds__(256)
ln_kernel(const float* __restrict__ gamma, const float* __restrict__ beta,
          float* __restrict__ out)
{
    const int row = blockIdx.x;
    const int tid = threadIdx.x;
    const int lane = tid & 31;
    const int warp = tid >> 5;
    const float* y = g_y + (size_t)row * DD;

    float v[3];
    float s = 0.f, sq = 0.f;
#pragma unroll
    for (int j = 0; j < 3; j++) {
        v[j] = y[tid + j * 256];
        s += v[j];
        sq += v[j] * v[j];
    }
#pragma unroll
    for (int d2 = 16; d2 > 0; d2 >>= 1) {
        s  += __shfl_xor_sync(0xffffffffu, s, d2);
        sq += __shfl_xor_sync(0xffffffffu, sq, d2);
    }
    __shared__ float rs[8], rq[8];
    if (lane == 0) { rs[warp] = s; rq[warp] = sq; }
    __syncthreads();
    if (warp == 0) {
        float a  = (lane < 8) ? rs[lane] : 0.f;
        float b2 = (lane < 8) ? rq[lane] : 0.f;
#pragma unroll
        for (int d2 = 4; d2 > 0; d2 >>= 1) {
            a  += __shfl_xor_sync(0xffffffffu, a, d2);
            b2 += __shfl_xor_sync(0xffffffffu, b2, d2);
        }
        if (lane == 0) { rs[0] = a; rq[0] = b2; }
    }
    __syncthreads();
    const float mu   = rs[0] * (1.f / 768.f);
    const float var  = rq[0] * (1.f / 768.f) - mu * mu;
    const float rstd = rsqrtf(var + 1e-5f);
#pragma unroll
    for (int j = 0; j < 3; j++) {
        int i = tid + j * 256;
        out[(size_t)row * DD + i] = (v[j] - mu) * rstd * gamma[i] + beta[i];
    }
}

// ===========================================================================
extern "C" void kernel_launch(void* const* d_in, const int* in_sizes, int n_in,
                              void* d_out, int out_size)
{
    const float* x     = (const float*)d_in[0];
    const float* Wq    = (const float*)d_in[1];
    const float* bq    = (const float*)d_in[2];
    const float* Wk    = (const float*)d_in[3];
    const float* bk    = (const float*)d_in[4];
    const float* Wv    = (const float*)d_in[5];
    const float* bv    = (const float*)d_in[6];
    const float* Wo    = (const float*)d_in[7];
    const float* bo    = (const float*)d_in[8];
    const float* gamma = (const float*)d_in[9];
    const float* beta  = (const float*)d_in[10];
    float* out = (float*)d_out;

    cudaFuncSetAttribute(gemm_h, cudaFuncAttributeMaxDynamicSharedMemorySize, GSMEM);

    f2h_kernel<<<(MM * DD) / (256 * 8), 256>>>(x);

    dim3 tg(DD / 32, DD / 32);
    transpose_w<<<tg, dim3(32, 8)>>>(Wq, 0);
    transpose_w<<<tg, dim3(32, 8)>>>(Wk, 1);
    transpose_w<<<tg, dim3(32, 8)>>>(Wv, 2);
    transpose_w<<<tg, dim3(32, 8)>>>(Wo, 3);

    dim3 gg(DD / 128, MM / 128);   // (6, 256)
    gemm_h<<<gg, 256, GSMEM>>>(0, bq, nullptr, 0, 0);
    gemm_h<<<gg, 256, GSMEM>>>(0, bk, nullptr, 1, 1);
    gemm_h<<<gg, 256, GSMEM>>>(0, bv, nullptr, 2, 2);

    attn_kernel<<<(BB * TT * HH) / 8, 256>>>();

    gemm_h<<<gg, 256, GSMEM>>>(1, bo, x, 3, 3);

    ln_kernel<<<MM, 256>>>(gamma, beta, out);
}